// round 7
// baseline (speedup 1.0000x reference)
#include <cuda_runtime.h>
#include <cuda_bf16.h>
#include <cstdint>
#include <cstddef>

#define BB 8
#define NN 2048
#define IND 256
#define DD 64
#define ALPHA 0.2f
#define KTILE 64
#define NKT (NN / KTILE)   // 32

// ---------------- device scratch (allocation-free) ----------------
__device__ float g_s1[BB * NN];
__device__ float g_s2[BB * NN];
// hi half at [0, BB*DD*NN), lo half at +BB*DD*NN elements. layout [b][d][j]
__device__ __nv_bfloat16 g_B[(size_t)2 * BB * DD * NN];
#define LOOFF ((size_t)BB * DD * NN * 2)   // byte offset hi -> lo

// ---------------- helpers ----------------
__device__ __forceinline__ uint32_t smem_u32(const void* p) {
    uint32_t a;
    asm("{ .reg .u64 t; cvta.to.shared.u64 t, %1; cvt.u32.u64 %0, t; }"
        : "=r"(a) : "l"(p));
    return a;
}
__device__ __forceinline__ unsigned long long pack2(float x, float y) {
    unsigned long long d;
    asm("mov.b64 %0, {%1, %2};" : "=l"(d) : "f"(x), "f"(y));
    return d;
}
__device__ __forceinline__ unsigned long long ffma2(unsigned long long a,
                                                    unsigned long long b,
                                                    unsigned long long c) {
    unsigned long long d;
    asm("fma.rn.f32x2 %0, %1, %2, %3;" : "=l"(d) : "l"(a), "l"(b), "l"(c));
    return d;
}
__device__ __forceinline__ float lo32(unsigned long long v) {
    return __uint_as_float((unsigned)(v & 0xffffffffull));
}
__device__ __forceinline__ float hi32(unsigned long long v) {
    return __uint_as_float((unsigned)(v >> 32));
}
// pack (first, second) -> bf16x2 with first in LOW half
__device__ __forceinline__ uint32_t bf2(float first, float second) {
    uint32_t r;
    asm("cvt.rn.bf16x2.f32 %0, %1, %2;" : "=r"(r) : "f"(second), "f"(first));
    return r;
}
__device__ __forceinline__ uint32_t sw128(uint32_t off) {
    return off ^ ((off >> 3) & 0x70);
}
__device__ __forceinline__ void ldmx4(uint32_t& r0, uint32_t& r1, uint32_t& r2,
                                      uint32_t& r3, uint32_t addr) {
    asm volatile("ldmatrix.sync.aligned.m8n8.x4.shared.b16 {%0,%1,%2,%3}, [%4];"
                 : "=r"(r0), "=r"(r1), "=r"(r2), "=r"(r3) : "r"(addr));
}
__device__ __forceinline__ void mma16816(float* d, uint32_t a0, uint32_t a1,
                                         uint32_t a2, uint32_t a3, uint32_t b0,
                                         uint32_t b1) {
    asm volatile(
        "mma.sync.aligned.m16n8k16.row.col.f32.bf16.bf16.f32 "
        "{%0,%1,%2,%3}, {%4,%5,%6,%7}, {%8,%9}, {%0,%1,%2,%3};"
        : "+f"(d[0]), "+f"(d[1]), "+f"(d[2]), "+f"(d[3])
        : "r"(a0), "r"(a1), "r"(a2), "r"(a3), "r"(b0), "r"(b1));
}
__device__ __forceinline__ float pe(float e, int m) {
    e = fmaxf(e, ALPHA * e);
    return m ? __expf(e) : 0.f;
}
__device__ __forceinline__ void cpa16(uint32_t dst, const void* src) {
    asm volatile("cp.async.cg.shared.global [%0], [%1], 16;"
                 :: "r"(dst), "l"(src) : "memory");
}
__device__ __forceinline__ void cpa_commit() {
    asm volatile("cp.async.commit_group;" ::: "memory");
}
__device__ __forceinline__ void cpa_wait0() {
    asm volatile("cp.async.wait_group 0;" ::: "memory");
}

// ================= Kernel 1: fused Wh + s1/s2 + bf16-split B operand =================
// 128 threads, 32 rows/CTA, grid 256. Thread = 2 rows x 8 cols (f32x2 col pairs).
// W double-buffered in 16KB k-chunks via cp.async; h served by L1 (8-way reuse).
__global__ void __launch_bounds__(128) wh_kernel(const float* __restrict__ h,
                                                 const float* __restrict__ W,
                                                 const float* __restrict__ a) {
    __shared__ float wbuf[2][64 * 64];   // 2 x 16KB
    __shared__ float ws[32][68];
    __shared__ float a_s[2 * DD];
    const int tid = threadIdx.x;
    const int row0 = blockIdx.x * 32;
    const int rowg = tid >> 3;           // 0..15 (2 rows each)
    const int c0 = (tid & 7) * 8;        // 8 cols

    if (tid < 2 * DD) a_s[tid] = a[tid];

    const uint32_t wsm0 = smem_u32(&wbuf[0][0]);
    const uint32_t wsm1 = smem_u32(&wbuf[1][0]);

#define STAGEW(c)                                                          \
    do {                                                                   \
        const uint32_t wd = ((c) & 1) ? wsm1 : wsm0;                       \
        _Pragma("unroll")                                                  \
        for (int q = 0; q < 8; q++) {                                      \
            const int idx = tid + 128 * q;                                 \
            cpa16(wd + idx * 16, W + (c) * 4096 + idx * 4);                \
        }                                                                  \
    } while (0)

    STAGEW(0);
    cpa_commit();

    unsigned long long acc[8];
#pragma unroll
    for (int q = 0; q < 8; q++) acc[q] = 0ull;

    const float* hrow = h + (size_t)(row0 + rowg * 2) * IND;

    for (int c = 0; c < 4; c++) {
        cpa_wait0();
        __syncthreads();
        if (c < 3) {
            STAGEW(c + 1);
            cpa_commit();
        }
        const float* base = (c & 1) ? &wbuf[1][0] : &wbuf[0][0];
#pragma unroll 4
        for (int k = 0; k < 64; k++) {
            const int kk = c * 64 + k;
            const float h0 = hrow[kk];
            const float h1 = hrow[IND + kk];
            const unsigned long long hp0 = pack2(h0, h0);
            const unsigned long long hp1 = pack2(h1, h1);
#pragma unroll
            for (int m = 0; m < 4; m++) {
                const unsigned long long wv =
                    *(const unsigned long long*)&base[k * 64 + c0 + 2 * m];
                acc[m] = ffma2(hp0, wv, acc[m]);
                acc[4 + m] = ffma2(hp1, wv, acc[4 + m]);
            }
        }
    }
#undef STAGEW

    // results -> ws
#pragma unroll
    for (int rr = 0; rr < 2; rr++)
#pragma unroll
        for (int m = 0; m < 4; m++) {
            const unsigned long long v = acc[rr * 4 + m];
            *(float2*)&ws[rowg * 2 + rr][c0 + 2 * m] = make_float2(lo32(v), hi32(v));
        }
    __syncthreads();

    // s1/s2 (warp 0, one row per lane)
    if (tid < 32) {
        float s1 = 0.f, s2 = 0.f;
#pragma unroll 8
        for (int c = 0; c < DD; c++) {
            const float v = ws[tid][c];
            s1 = fmaf(v, a_s[c], s1);
            s2 = fmaf(v, a_s[DD + c], s2);
        }
        g_s1[row0 + tid] = s1;
        g_s2[row0 + tid] = s2;
    }

    // bf16-split transpose: thread d = tid&63 writes 16 j's (rows rg*16..+15)
    {
        const int d = tid & 63, rg = tid >> 6;
        uint32_t hi8[8], lo8[8];
#pragma unroll
        for (int p = 0; p < 8; p++) {
            const float p0 = ws[rg * 16 + 2 * p][d];
            const float p1 = ws[rg * 16 + 2 * p + 1][d];
            const uint32_t h2 = bf2(p0, p1);
            const float f0 = __uint_as_float(h2 << 16);
            const float f1 = __uint_as_float(h2 & 0xffff0000u);
            hi8[p] = h2;
            lo8[p] = bf2(p0 - f0, p1 - f1);
        }
        const size_t bb = (size_t)(row0 >> 11);
        const int j0l = (row0 & (NN - 1)) + rg * 16;
        char* dst = (char*)g_B + ((bb * DD + d) * NN + j0l) * 2;
        *(uint4*)(dst) = make_uint4(hi8[0], hi8[1], hi8[2], hi8[3]);
        *(uint4*)(dst + 16) = make_uint4(hi8[4], hi8[5], hi8[6], hi8[7]);
        *(uint4*)(dst + LOOFF) = make_uint4(lo8[0], lo8[1], lo8[2], lo8[3]);
        *(uint4*)(dst + LOOFF + 16) = make_uint4(lo8[4], lo8[5], lo8[6], lo8[7]);
    }
}

// ================= Kernel 2: masked-softmax x Wh =================
// 256 threads, 32 rows/CTA, grid 512. 8 warps = 2 wrow x 2 nsplit x 2 ksplit.
#define BUFSZ 16384
#define DSM_BYTES (4 * BUFSZ + 1024)

__global__ void __launch_bounds__(256, 3) attn_kernel(const int* __restrict__ adj,
                                                      float* __restrict__ out) {
    extern __shared__ uint8_t dsm_raw[];
    uint32_t sb = smem_u32(dsm_raw);
    sb = (sb + 1023u) & ~1023u;

    const int tid = threadIdx.x, wid = tid >> 5, lid = tid & 31;
    const int kg = wid & 1;              // k-split half
    const int ns = (wid >> 1) & 1;       // n-split half (cols ns*32..)
    const int wrow = wid >> 2;           // 0..1 (16-row blocks)
    const int b = blockIdx.x >> 6;       // 64 CTAs per batch
    const int i0 = (blockIdx.x & 63) * 32;
    const int ibase = i0 + wrow * 16;
    const int r0 = lid >> 2, c0 = (lid & 3) * 2;

    const float s1_0 = g_s1[b * NN + ibase + r0];
    const float s1_1 = g_s1[b * NN + ibase + r0 + 8];
    float den0 = 0.f, den1 = 0.f;
    float4 acc[4];
#pragma unroll
    for (int nt = 0; nt < 4; nt++) acc[nt] = make_float4(0.f, 0.f, 0.f, 0.f);
    const float* s2base = g_s2 + b * NN;

    uint32_t nrel0, nrel1, nxor0, nxor1, kh;
    {
        const int g = lid >> 3, rowin = lid & 7;
        kh = (uint32_t)((g & 1) * 16);
        const int n0 = ns * 32 + (g >> 1) * 8 + rowin;
        const int n1 = n0 + 16;
        nrel0 = (uint32_t)(n0 * 128);
        nxor0 = (uint32_t)((n0 & 7) << 4);
        nrel1 = (uint32_t)(n1 * 128);
        nxor1 = (uint32_t)((n1 & 7) << 4);
    }

    // staging: 256 threads x 2 chunks cover 64 d x 8 ch (hi) + same (lo)
    const char* gbh = (const char*)g_B + (size_t)b * DD * NN * 2;
    const int e0 = tid, e1 = tid + 256;
    const uint32_t ssw0 = sw128((uint32_t)((e0 >> 3) * 128 + (e0 & 7) * 16));
    const uint32_t ssw1 = sw128((uint32_t)((e1 >> 3) * 128 + (e1 & 7) * 16));
    const uint32_t sgo0 = (uint32_t)((e0 >> 3) * NN * 2 + (e0 & 7) * 16);
    const uint32_t sgo1 = (uint32_t)((e1 >> 3) * NN * 2 + (e1 & 7) * 16);

    const int* arow0 = adj + (size_t)(b * NN + ibase + r0) * NN;

#define STAGE(t)                                                          \
    do {                                                                  \
        const uint32_t dstb = sb + (((t) & 3) * BUFSZ);                   \
        const size_t go = (size_t)(t) * (KTILE * 2);                      \
        cpa16(dstb + ssw0, gbh + sgo0 + go);                              \
        cpa16(dstb + ssw0 + 8192, gbh + sgo0 + go + LOOFF);               \
        cpa16(dstb + ssw1, gbh + sgo1 + go);                              \
        cpa16(dstb + ssw1 + 8192, gbh + sgo1 + go + LOOFF);               \
    } while (0)

    STAGE(0);
    STAGE(1);
    cpa_commit();

    for (int i = 0; i < NKT / 2; i++) {
        cpa_wait0();
        __syncthreads();
        if (i < NKT / 2 - 1) {
            STAGE(2 * i + 2);
            STAGE(2 * i + 3);
            cpa_commit();
        }

        const int t = 2 * i + kg;
        const uint32_t bufb = sb + ((t & 3) * BUFSZ);
        const int jb0 = t * KTILE;

#pragma unroll
        for (int ks = 0; ks < 4; ks++) {
            const int jc = jb0 + ks * 16 + c0;
            const int2 aj0 = *(const int2*)(arow0 + jc);
            const int2 aj1 = *(const int2*)(arow0 + jc + 8);
            const int2 aj2 = *(const int2*)(arow0 + 8 * NN + jc);
            const int2 aj3 = *(const int2*)(arow0 + 8 * NN + jc + 8);
            const float2 s2a = *(const float2*)(s2base + jc);
            const float2 s2b = *(const float2*)(s2base + jc + 8);

            const float p0 = pe(s1_0 + s2a.x, aj0.x);
            const float p1 = pe(s1_0 + s2a.y, aj0.y);
            const float p2 = pe(s1_0 + s2b.x, aj1.x);
            const float p3 = pe(s1_0 + s2b.y, aj1.y);
            const float p4 = pe(s1_1 + s2a.x, aj2.x);
            const float p5 = pe(s1_1 + s2a.y, aj2.y);
            const float p6 = pe(s1_1 + s2b.x, aj3.x);
            const float p7 = pe(s1_1 + s2b.y, aj3.y);
            den0 += (p0 + p1) + (p2 + p3);
            den1 += (p4 + p5) + (p6 + p7);

            uint32_t ah[4], al[4];
            {
                const uint32_t h0 = bf2(p0, p1), h1 = bf2(p4, p5);
                const uint32_t h2 = bf2(p2, p3), h3 = bf2(p6, p7);
                ah[0] = h0; ah[1] = h1; ah[2] = h2; ah[3] = h3;
                al[0] = bf2(p0 - __uint_as_float(h0 << 16),
                            p1 - __uint_as_float(h0 & 0xffff0000u));
                al[1] = bf2(p4 - __uint_as_float(h1 << 16),
                            p5 - __uint_as_float(h1 & 0xffff0000u));
                al[2] = bf2(p2 - __uint_as_float(h2 << 16),
                            p3 - __uint_as_float(h2 & 0xffff0000u));
                al[3] = bf2(p6 - __uint_as_float(h3 << 16),
                            p7 - __uint_as_float(h3 & 0xffff0000u));
            }

            const uint32_t koff = (uint32_t)(ks * 32) + kh;
            {
                const uint32_t addr = bufb + nrel0 + (koff ^ nxor0);
                uint32_t h0, h1, h2, h3, l0, l1, l2, l3;
                ldmx4(h0, h1, h2, h3, addr);
                ldmx4(l0, l1, l2, l3, addr + 8192);
                float* d0 = (float*)&acc[0];
                float* d1 = (float*)&acc[1];
                mma16816(d0, ah[0], ah[1], ah[2], ah[3], h0, h1);
                mma16816(d0, al[0], al[1], al[2], al[3], h0, h1);
                mma16816(d0, ah[0], ah[1], ah[2], ah[3], l0, l1);
                mma16816(d1, ah[0], ah[1], ah[2], ah[3], h2, h3);
                mma16816(d1, al[0], al[1], al[2], al[3], h2, h3);
                mma16816(d1, ah[0], ah[1], ah[2], ah[3], l2, l3);
            }
            {
                const uint32_t addr = bufb + nrel1 + (koff ^ nxor1);
                uint32_t h0, h1, h2, h3, l0, l1, l2, l3;
                ldmx4(h0, h1, h2, h3, addr);
                ldmx4(l0, l1, l2, l3, addr + 8192);
                float* d0 = (float*)&acc[2];
                float* d1 = (float*)&acc[3];
                mma16816(d0, ah[0], ah[1], ah[2], ah[3], h0, h1);
                mma16816(d0, al[0], al[1], al[2], al[3], h0, h1);
                mma16816(d0, ah[0], ah[1], ah[2], ah[3], l0, l1);
                mma16816(d1, ah[0], ah[1], ah[2], ah[3], h2, h3);
                mma16816(d1, al[0], al[1], al[2], al[3], h2, h3);
                mma16816(d1, ah[0], ah[1], ah[2], ah[3], l2, l3);
            }
        }
    }
#undef STAGE

    // ---- K-split reduction (region overlaps ring bufs 0/1; safe per barrier order) ----
    {
        float* redp = (float*)(dsm_raw + (sb - smem_u32(dsm_raw)));
        float* slot = redp + (size_t)(((wrow * 2 + ns) * 32 + lid)) * 20;  // 80B stride
        if (kg == 1) {
#pragma unroll
            for (int nt = 0; nt < 4; nt++) *(float4*)(slot + nt * 4) = acc[nt];
            slot[16] = den0;
            slot[17] = den1;
        }
        __syncthreads();
        if (kg == 0) {
#pragma unroll
            for (int nt = 0; nt < 4; nt++) {
                const float4 v = *(const float4*)(slot + nt * 4);
                acc[nt].x += v.x; acc[nt].y += v.y;
                acc[nt].z += v.z; acc[nt].w += v.w;
            }
            den0 += slot[16];
            den1 += slot[17];

            den0 += __shfl_xor_sync(0xffffffffu, den0, 1);
            den0 += __shfl_xor_sync(0xffffffffu, den0, 2);
            den1 += __shfl_xor_sync(0xffffffffu, den1, 1);
            den1 += __shfl_xor_sync(0xffffffffu, den1, 2);
            const float inv0 = 1.0f / den0;
            const float inv1 = 1.0f / den1;

            float* o0 = out + (size_t)(b * NN + ibase + r0) * DD + ns * 32;
            float* o1 = o0 + (size_t)8 * DD;
#pragma unroll
            for (int nt = 0; nt < 4; nt++) {
                *(float2*)(o0 + nt * 8 + c0) =
                    make_float2(acc[nt].x * inv0, acc[nt].y * inv0);
                *(float2*)(o1 + nt * 8 + c0) =
                    make_float2(acc[nt].z * inv1, acc[nt].w * inv1);
            }
        }
    }
}

extern "C" void kernel_launch(void* const* d_in, const int* in_sizes, int n_in,
                              void* d_out, int out_size) {
    const float* h = nullptr;
    const int* adj = nullptr;
    const float* W = nullptr;
    const float* a = nullptr;
    for (int i = 0; i < n_in; i++) {
        const long long s = in_sizes[i];
        if (s == (long long)BB * NN * IND)      h   = (const float*)d_in[i];
        else if (s == (long long)BB * NN * NN)  adj = (const int*)d_in[i];
        else if (s == (long long)IND * DD)      W   = (const float*)d_in[i];
        else if (s == 2 * DD)                   a   = (const float*)d_in[i];
    }
    float* out = (float*)d_out;

    static bool attr_set = false;
    if (!attr_set) {
        cudaFuncSetAttribute(attn_kernel, cudaFuncAttributeMaxDynamicSharedMemorySize,
                             DSM_BYTES);
        attr_set = true;
    }

    wh_kernel<<<(BB * NN) / 32, 128>>>(h, W, a);
    attn_kernel<<<BB * (NN / 32), 256, DSM_BYTES>>>(adj, out);
}

// round 10
// speedup vs baseline: 1.9073x; 1.9073x over previous
#include <cuda_runtime.h>
#include <cuda_bf16.h>
#include <cstdint>
#include <cstddef>

#define BB 8
#define NN 2048
#define IND 256
#define DD 64
#define ALPHA 0.2f
#define KTILE 64
#define NKT (NN / KTILE)   // 32

// ---------------- device scratch (allocation-free) ----------------
__device__ float g_s1[BB * NN];
__device__ float g_s2[BB * NN];
// hi half at [0, BB*DD*NN), lo half at +BB*DD*NN elements. layout [b][d][j]
__device__ __nv_bfloat16 g_B[(size_t)2 * BB * DD * NN];
#define LOOFF ((size_t)BB * DD * NN * 2)   // byte offset hi -> lo

// ---------------- helpers ----------------
__device__ __forceinline__ uint32_t smem_u32(const void* p) {
    uint32_t a;
    asm("{ .reg .u64 t; cvta.to.shared.u64 t, %1; cvt.u32.u64 %0, t; }"
        : "=r"(a) : "l"(p));
    return a;
}
__device__ __forceinline__ unsigned long long pack2(float x, float y) {
    unsigned long long d;
    asm("mov.b64 %0, {%1, %2};" : "=l"(d) : "f"(x), "f"(y));
    return d;
}
__device__ __forceinline__ unsigned long long ffma2(unsigned long long a,
                                                    unsigned long long b,
                                                    unsigned long long c) {
    unsigned long long d;
    asm("fma.rn.f32x2 %0, %1, %2, %3;" : "=l"(d) : "l"(a), "l"(b), "l"(c));
    return d;
}
__device__ __forceinline__ float lo32(unsigned long long v) {
    return __uint_as_float((unsigned)(v & 0xffffffffull));
}
__device__ __forceinline__ float hi32(unsigned long long v) {
    return __uint_as_float((unsigned)(v >> 32));
}
// pack (first, second) -> bf16x2 with first in LOW half
__device__ __forceinline__ uint32_t bf2(float first, float second) {
    uint32_t r;
    asm("cvt.rn.bf16x2.f32 %0, %1, %2;" : "=r"(r) : "f"(second), "f"(first));
    return r;
}
__device__ __forceinline__ uint32_t sw128(uint32_t off) {
    return off ^ ((off >> 3) & 0x70);
}
__device__ __forceinline__ void ldmx4(uint32_t& r0, uint32_t& r1, uint32_t& r2,
                                      uint32_t& r3, uint32_t addr) {
    asm volatile("ldmatrix.sync.aligned.m8n8.x4.shared.b16 {%0,%1,%2,%3}, [%4];"
                 : "=r"(r0), "=r"(r1), "=r"(r2), "=r"(r3) : "r"(addr));
}
__device__ __forceinline__ void mma16816(float* d, uint32_t a0, uint32_t a1,
                                         uint32_t a2, uint32_t a3, uint32_t b0,
                                         uint32_t b1) {
    asm volatile(
        "mma.sync.aligned.m16n8k16.row.col.f32.bf16.bf16.f32 "
        "{%0,%1,%2,%3}, {%4,%5,%6,%7}, {%8,%9}, {%0,%1,%2,%3};"
        : "+f"(d[0]), "+f"(d[1]), "+f"(d[2]), "+f"(d[3])
        : "r"(a0), "r"(a1), "r"(a2), "r"(a3), "r"(b0), "r"(b1));
}
__device__ __forceinline__ float pe(float e, int m) {
    e = fmaxf(e, ALPHA * e);
    return m ? __expf(e) : 0.f;
}
__device__ __forceinline__ void cpa16(uint32_t dst, const void* src) {
    asm volatile("cp.async.cg.shared.global [%0], [%1], 16;"
                 :: "r"(dst), "l"(src) : "memory");
}
__device__ __forceinline__ void cpa_commit() {
    asm volatile("cp.async.commit_group;" ::: "memory");
}
__device__ __forceinline__ void cpa_wait0() {
    asm volatile("cp.async.wait_group 0;" ::: "memory");
}
__device__ __forceinline__ int2 lds_i2(uint32_t a) {
    int2 v;
    asm volatile("ld.shared.v2.b32 {%0,%1}, [%2];" : "=r"(v.x), "=r"(v.y) : "r"(a));
    return v;
}
__device__ __forceinline__ float2 lds_f2(uint32_t a) {
    float2 v;
    asm volatile("ld.shared.v2.f32 {%0,%1}, [%2];" : "=f"(v.x), "=f"(v.y) : "r"(a));
    return v;
}

// ================= Kernel 1: fused Wh + s1/s2 + bf16-split B operand =================
// 256 threads, 32 rows/CTA, grid 512. h streamed in 8KB k-chunks (cp.async, 2-deep).
__global__ void __launch_bounds__(256) wh_kernel(const float* __restrict__ h,
                                                 const float* __restrict__ W,
                                                 const float* __restrict__ a) {
    __shared__ float hbuf[2][32 * 64];   // 2 x 8 KB
    __shared__ float ws[32][68];
    __shared__ float a_s[2 * DD];
    const int tid = threadIdx.x;
    const int row0 = blockIdx.x * 32;

    if (tid < 2 * DD) a_s[tid] = a[tid];

    const char* hsrc = (const char*)(h + (size_t)row0 * IND);
    const uint32_t hb0 = smem_u32(&hbuf[0][0]);
    const uint32_t hb1 = smem_u32(&hbuf[1][0]);

#define STAGEH(c)                                                            \
    do {                                                                     \
        const uint32_t hd = ((c) & 1) ? hb1 : hb0;                           \
        _Pragma("unroll")                                                    \
        for (int q = 0; q < 2; q++) {                                        \
            const int idx = tid + 256 * q;                                   \
            const int r = idx >> 4, ch = idx & 15;                           \
            cpa16(hd + idx * 16, hsrc + (size_t)r * 1024 + (c) * 256 + ch * 16); \
        }                                                                    \
    } while (0)

    STAGEH(0);
    cpa_commit();

    const int ccol = tid & 63, rq = tid >> 6;
    unsigned long long acc[8];
#pragma unroll
    for (int q = 0; q < 8; q++) acc[q] = 0ull;

    for (int c = 0; c < 4; c++) {
        cpa_wait0();
        __syncthreads();
        if (c < 3) {
            STAGEH(c + 1);
            cpa_commit();
        }
        const float* hbp = (c & 1) ? &hbuf[1][0] : &hbuf[0][0];
#pragma unroll 8
        for (int k2 = 0; k2 < 32; k2++) {
            const int kk = c * 64 + 2 * k2;
            const float w0 = __ldg(&W[kk * DD + ccol]);
            const float w1 = __ldg(&W[(kk + 1) * DD + ccol]);
            const unsigned long long w2 = pack2(w0, w1);
#pragma unroll
            for (int rr = 0; rr < 8; rr++) {
                const unsigned long long hv =
                    *(const unsigned long long*)&hbp[(rq * 8 + rr) * 64 + 2 * k2];
                acc[rr] = ffma2(hv, w2, acc[rr]);
            }
        }
    }
#undef STAGEH

#pragma unroll
    for (int rr = 0; rr < 8; rr++)
        ws[rq * 8 + rr][ccol] = lo32(acc[rr]) + hi32(acc[rr]);
    __syncthreads();

    // s1/s2: warp w handles rows 4w..4w+3
    {
        const int w = tid >> 5, l = tid & 31;
        const int row = 4 * w + (l >> 3);
        const int c8 = (l & 7) * 8;
        const float4 v0 = *(float4*)&ws[row][c8];
        const float4 v1 = *(float4*)&ws[row][c8 + 4];
        const float4 x0 = *(const float4*)&a_s[c8];
        const float4 x1 = *(const float4*)&a_s[c8 + 4];
        const float4 y0 = *(const float4*)&a_s[DD + c8];
        const float4 y1 = *(const float4*)&a_s[DD + c8 + 4];
        float s1p = v0.x * x0.x + v0.y * x0.y + v0.z * x0.z + v0.w * x0.w +
                    v1.x * x1.x + v1.y * x1.y + v1.z * x1.z + v1.w * x1.w;
        float s2p = v0.x * y0.x + v0.y * y0.y + v0.z * y0.z + v0.w * y0.w +
                    v1.x * y1.x + v1.y * y1.y + v1.z * y1.z + v1.w * y1.w;
#pragma unroll
        for (int o = 1; o < 8; o <<= 1) {
            s1p += __shfl_xor_sync(0xffffffffu, s1p, o);
            s2p += __shfl_xor_sync(0xffffffffu, s2p, o);
        }
        if ((l & 7) == 0) {
            g_s1[row0 + row] = s1p;
            g_s2[row0 + row] = s2p;
        }
    }

    // bf16-split transpose
    {
        const int d = tid & 63, rg = tid >> 6;
        uint32_t hi4[4], lo4[4];
#pragma unroll
        for (int p = 0; p < 4; p++) {
            const float p0 = ws[rg * 8 + 2 * p][d];
            const float p1 = ws[rg * 8 + 2 * p + 1][d];
            const uint32_t h2 = bf2(p0, p1);
            const float f0 = __uint_as_float(h2 << 16);
            const float f1 = __uint_as_float(h2 & 0xffff0000u);
            hi4[p] = h2;
            lo4[p] = bf2(p0 - f0, p1 - f1);
        }
        const size_t bb = (size_t)(row0 >> 11);
        const int j0l = (row0 & (NN - 1)) + rg * 8;
        char* dst = (char*)g_B + ((bb * DD + d) * NN + j0l) * 2;
        *(uint4*)(dst) = make_uint4(hi4[0], hi4[1], hi4[2], hi4[3]);
        *(uint4*)(dst + LOOFF) = make_uint4(lo4[0], lo4[1], lo4[2], lo4[3]);
    }
}

// ================= Kernel 2: masked-softmax x Wh, adj staged via cp.async =================
// 512 threads, 128 rows/CTA, grid 128. 16 warps = 8 row-blocks x 2 K-split.
// dyn smem: 4 x [B 16KB] at 0, 4 x [adj 34KB] at 64KB, s2 8KB at 200KB.
#define BSTG 16384
#define ASTG 34816                 // 128 rows * 272 B (row pad for conflict-free LDS)
#define AOFF (4 * BSTG)            // 65536
#define S2OFF (AOFF + 4 * ASTG)    // 204800
#define DSM_BYTES (S2OFF + 8192 + 1024)

__global__ void __launch_bounds__(512, 1) attn_kernel(const int* __restrict__ adj,
                                                      float* __restrict__ out) {
    extern __shared__ uint8_t dsm_raw[];
    uint32_t sb = smem_u32(dsm_raw);
    sb = (sb + 1023u) & ~1023u;

    const int tid = threadIdx.x, wid = tid >> 5, lid = tid & 31;
    const int wg = wid >> 3;        // 0: even tiles, 1: odd tiles
    const int wrow = wid & 7;       // row-block within CTA
    const int b = blockIdx.x >> 4;
    const int i0 = (blockIdx.x & 15) * 128;
    const int ibase = i0 + wrow * 16;
    const int r0 = lid >> 2, c0 = (lid & 3) * 2;

    const float s1_0 = g_s1[b * NN + ibase + r0];
    const float s1_1 = g_s1[b * NN + ibase + r0 + 8];
    float den0 = 0.f, den1 = 0.f;
    float4 acc[8];
#pragma unroll
    for (int nt = 0; nt < 8; nt++) acc[nt] = make_float4(0.f, 0.f, 0.f, 0.f);

    uint32_t nrel[4], nxor[4], kh;
    {
        const int g = lid >> 3, rowin = lid & 7;
        kh = (uint32_t)((g & 1) * 16);
#pragma unroll
        for (int np = 0; np < 4; np++) {
            const int n = np * 16 + (g >> 1) * 8 + rowin;
            nrel[np] = (uint32_t)(n * 128);
            nxor[np] = (uint32_t)((n & 7) << 4);
        }
    }

    // B staging (1 hi + 1 lo chunk per thread)
    const char* gbh = (const char*)g_B + (size_t)b * DD * NN * 2;
    const uint32_t ssw0 = sw128((uint32_t)((tid >> 3) * 128 + (tid & 7) * 16));
    const uint32_t sgo0 = (uint32_t)((tid >> 3) * NN * 2 + (tid & 7) * 16);

    // adj staging (4 chunks per thread)
    const char* gadj = (const char*)(adj + ((size_t)b * NN + i0) * NN);

#define STAGE(t)                                                               \
    do {                                                                       \
        const uint32_t bd = sb + (((t) & 3) * BSTG);                           \
        const size_t go = (size_t)(t) * (KTILE * 2);                           \
        cpa16(bd + ssw0, gbh + sgo0 + go);                                     \
        cpa16(bd + ssw0 + 8192, gbh + sgo0 + go + LOOFF);                      \
        const uint32_t ad = sb + AOFF + (((t) & 3) * ASTG);                    \
        const size_t jb = (size_t)(t) * (KTILE * 4);                           \
        _Pragma("unroll")                                                      \
        for (int q = 0; q < 4; q++) {                                          \
            const int idx = tid + 512 * q;                                     \
            const int rr_ = idx >> 4, ch_ = idx & 15;                          \
            cpa16(ad + rr_ * 272 + ch_ * 16,                                   \
                  gadj + (size_t)rr_ * (NN * 4) + jb + ch_ * 16);              \
        }                                                                      \
    } while (0)

    // s2 stage (once) + first two tiles
    cpa16(sb + S2OFF + tid * 16, (const char*)(g_s2 + b * NN) + tid * 16);
    STAGE(0);
    STAGE(1);
    cpa_commit();

    const uint32_t arow_base = (uint32_t)((wrow * 16 + r0) * 272);

    for (int i = 0; i < NKT / 2; i++) {
        cpa_wait0();
        __syncthreads();
        if (i < NKT / 2 - 1) {
            STAGE(2 * i + 2);
            STAGE(2 * i + 3);
            cpa_commit();
        }

        const int t = 2 * i + wg;
        const uint32_t bufb = sb + ((t & 3) * BSTG);
        const uint32_t abuf = sb + AOFF + ((t & 3) * ASTG) + arow_base;

#pragma unroll
        for (int ks = 0; ks < 4; ks++) {
            const uint32_t jcb = (uint32_t)((ks * 16 + c0) * 4);
            const int2 aj0 = lds_i2(abuf + jcb);
            const int2 aj1 = lds_i2(abuf + jcb + 32);
            const int2 aj2 = lds_i2(abuf + 8 * 272 + jcb);
            const int2 aj3 = lds_i2(abuf + 8 * 272 + jcb + 32);
            const uint32_t s2ad = sb + S2OFF + (uint32_t)((t * 64 + ks * 16 + c0) * 4);
            const float2 s2a = lds_f2(s2ad);
            const float2 s2b = lds_f2(s2ad + 32);

            const float p0 = pe(s1_0 + s2a.x, aj0.x);
            const float p1 = pe(s1_0 + s2a.y, aj0.y);
            const float p2 = pe(s1_0 + s2b.x, aj1.x);
            const float p3 = pe(s1_0 + s2b.y, aj1.y);
            const float p4 = pe(s1_1 + s2a.x, aj2.x);
            const float p5 = pe(s1_1 + s2a.y, aj2.y);
            const float p6 = pe(s1_1 + s2b.x, aj3.x);
            const float p7 = pe(s1_1 + s2b.y, aj3.y);
            den0 += (p0 + p1) + (p2 + p3);
            den1 += (p4 + p5) + (p6 + p7);

            uint32_t ah[4], al[4];
            {
                const uint32_t h0 = bf2(p0, p1), h1 = bf2(p4, p5);
                const uint32_t h2 = bf2(p2, p3), h3 = bf2(p6, p7);
                ah[0] = h0; ah[1] = h1; ah[2] = h2; ah[3] = h3;
                al[0] = bf2(p0 - __uint_as_float(h0 << 16),
                            p1 - __uint_as_float(h0 & 0xffff0000u));
                al[1] = bf2(p4 - __uint_as_float(h1 << 16),
                            p5 - __uint_as_float(h1 & 0xffff0000u));
                al[2] = bf2(p2 - __uint_as_float(h2 << 16),
                            p3 - __uint_as_float(h2 & 0xffff0000u));
                al[3] = bf2(p6 - __uint_as_float(h3 << 16),
                            p7 - __uint_as_float(h3 & 0xffff0000u));
            }

#pragma unroll
            for (int np = 0; np < 4; np++) {
                const uint32_t off = ((uint32_t)(ks * 32) + kh) ^ nxor[np];
                const uint32_t addr = bufb + nrel[np] + off;
                uint32_t h0, h1, h2, h3, l0, l1, l2, l3;
                ldmx4(h0, h1, h2, h3, addr);
                ldmx4(l0, l1, l2, l3, addr + 8192);
                float* d0 = (float*)&acc[2 * np];
                float* d1 = (float*)&acc[2 * np + 1];
                mma16816(d0, ah[0], ah[1], ah[2], ah[3], h0, h1);
                mma16816(d0, al[0], al[1], al[2], al[3], h0, h1);
                mma16816(d0, ah[0], ah[1], ah[2], ah[3], l0, l1);
                mma16816(d1, ah[0], ah[1], ah[2], ah[3], h2, h3);
                mma16816(d1, al[0], al[1], al[2], al[3], h2, h3);
                mma16816(d1, ah[0], ah[1], ah[2], ah[3], l2, l3);
            }
        }
    }
#undef STAGE

    // all compute done before reduction region (overlaps B ring) is written
    __syncthreads();

    // ---- cross-group reduction: wg1 dumps partials, wg0 combines + stores ----
    {
        float* redp = (float*)(dsm_raw + (sb - smem_u32(dsm_raw)));
        float* slot = redp + (size_t)(wrow * 32 + lid) * 36;
        if (wg == 1) {
#pragma unroll
            for (int nt = 0; nt < 8; nt++) *(float4*)(slot + nt * 4) = acc[nt];
            slot[32] = den0;
            slot[33] = den1;
        }
        __syncthreads();
        if (wg == 0) {
#pragma unroll
            for (int nt = 0; nt < 8; nt++) {
                const float4 v = *(const float4*)(slot + nt * 4);
                acc[nt].x += v.x; acc[nt].y += v.y;
                acc[nt].z += v.z; acc[nt].w += v.w;
            }
            den0 += slot[32];
            den1 += slot[33];

            den0 += __shfl_xor_sync(0xffffffffu, den0, 1);
            den0 += __shfl_xor_sync(0xffffffffu, den0, 2);
            den1 += __shfl_xor_sync(0xffffffffu, den1, 1);
            den1 += __shfl_xor_sync(0xffffffffu, den1, 2);
            const float inv0 = 1.0f / den0;
            const float inv1 = 1.0f / den1;

            float* o0 = out + (size_t)(b * NN + ibase + r0) * DD;
            float* o1 = o0 + (size_t)8 * DD;
#pragma unroll
            for (int nt = 0; nt < 8; nt++) {
                *(float2*)(o0 + nt * 8 + c0) =
                    make_float2(acc[nt].x * inv0, acc[nt].y * inv0);
                *(float2*)(o1 + nt * 8 + c0) =
                    make_float2(acc[nt].z * inv1, acc[nt].w * inv1);
            }
        }
    }
}

extern "C" void kernel_launch(void* const* d_in, const int* in_sizes, int n_in,
                              void* d_out, int out_size) {
    const float* h = nullptr;
    const int* adj = nullptr;
    const float* W = nullptr;
    const float* a = nullptr;
    for (int i = 0; i < n_in; i++) {
        const long long s = in_sizes[i];
        if (s == (long long)BB * NN * IND)      h   = (const float*)d_in[i];
        else if (s == (long long)BB * NN * NN)  adj = (const int*)d_in[i];
        else if (s == (long long)IND * DD)      W   = (const float*)d_in[i];
        else if (s == 2 * DD)                   a   = (const float*)d_in[i];
    }
    float* out = (float*)d_out;

    static bool attr_set = false;
    if (!attr_set) {
        cudaFuncSetAttribute(attn_kernel, cudaFuncAttributeMaxDynamicSharedMemorySize,
                             DSM_BYTES);
        attr_set = true;
    }

    wh_kernel<<<(BB * NN) / 32, 256>>>(h, W, a);
    attn_kernel<<<BB * (NN / 128), 512, DSM_BYTES>>>(adj, out);
}

// round 11
// speedup vs baseline: 2.1717x; 1.1386x over previous
#include <cuda_runtime.h>
#include <cuda_bf16.h>
#include <cstdint>
#include <cstddef>

#define BB 8
#define NN 2048
#define IND 256
#define DD 64
#define ALPHA 0.2f
#define KTILE 64
#define NKT (NN / KTILE)   // 32

// ---------------- device scratch (allocation-free) ----------------
__device__ float g_s1[BB * NN];
__device__ float g_s2[BB * NN];
// hi half at [0, BB*DD*NN), lo half at +BB*DD*NN elements. layout [b][d][j]
__device__ __nv_bfloat16 g_B[(size_t)2 * BB * DD * NN];
#define LOOFF ((size_t)BB * DD * NN * 2)   // byte offset hi -> lo

// ---------------- helpers ----------------
__device__ __forceinline__ uint32_t smem_u32(const void* p) {
    uint32_t a;
    asm("{ .reg .u64 t; cvta.to.shared.u64 t, %1; cvt.u32.u64 %0, t; }"
        : "=r"(a) : "l"(p));
    return a;
}
// pack (first, second) -> bf16x2 with first in LOW half
__device__ __forceinline__ uint32_t bf2(float first, float second) {
    uint32_t r;
    asm("cvt.rn.bf16x2.f32 %0, %1, %2;" : "=r"(r) : "f"(second), "f"(first));
    return r;
}
__device__ __forceinline__ uint32_t sw128(uint32_t off) {
    return off ^ ((off >> 3) & 0x70);
}
__device__ __forceinline__ void ldmx4(uint32_t& r0, uint32_t& r1, uint32_t& r2,
                                      uint32_t& r3, uint32_t addr) {
    asm volatile("ldmatrix.sync.aligned.m8n8.x4.shared.b16 {%0,%1,%2,%3}, [%4];"
                 : "=r"(r0), "=r"(r1), "=r"(r2), "=r"(r3) : "r"(addr));
}
__device__ __forceinline__ void mma16816(float* d, uint32_t a0, uint32_t a1,
                                         uint32_t a2, uint32_t a3, uint32_t b0,
                                         uint32_t b1) {
    asm volatile(
        "mma.sync.aligned.m16n8k16.row.col.f32.bf16.bf16.f32 "
        "{%0,%1,%2,%3}, {%4,%5,%6,%7}, {%8,%9}, {%0,%1,%2,%3};"
        : "+f"(d[0]), "+f"(d[1]), "+f"(d[2]), "+f"(d[3])
        : "r"(a0), "r"(a1), "r"(a2), "r"(a3), "r"(b0), "r"(b1));
}
__device__ __forceinline__ float pe(float e, int m) {
    e = fmaxf(e, ALPHA * e);
    return m ? __expf(e) : 0.f;
}
__device__ __forceinline__ void cpa16(uint32_t dst, const void* src) {
    asm volatile("cp.async.cg.shared.global [%0], [%1], 16;"
                 :: "r"(dst), "l"(src) : "memory");
}
__device__ __forceinline__ void cpa_commit() {
    asm volatile("cp.async.commit_group;" ::: "memory");
}
__device__ __forceinline__ void cpa_wait0() {
    asm volatile("cp.async.wait_group 0;" ::: "memory");
}
__device__ __forceinline__ int2 lds_i2(uint32_t a) {
    int2 v;
    asm volatile("ld.shared.v2.b32 {%0,%1}, [%2];" : "=r"(v.x), "=r"(v.y) : "r"(a));
    return v;
}
__device__ __forceinline__ float2 lds_f2(uint32_t a) {
    float2 v;
    asm volatile("ld.shared.v2.f32 {%0,%1}, [%2];" : "=f"(v.x), "=f"(v.y) : "r"(a));
    return v;
}
__device__ __forceinline__ void sts16(uint32_t a, uint16_t v) {
    asm volatile("st.shared.u16 [%0], %1;" :: "r"(a), "h"(v) : "memory");
}

// ================= Kernel 1: Wh = h @ W via mma.sync (bf16-split-3) =================
// 256 threads, 128 rows/CTA, grid 128. W split to smem once; h streamed fp32
// in 4 k-chunks (cp.async 2-deep). Epilogue: s1/s2 + bf16-split transpose.
#define WHI_OFF 0
#define WLO_OFF 32768
#define HB_OFF 65536
#define HBSZ 36864                 // 128 rows * 72 floats * 4
#define WS_OFF (HB_OFF + 2 * HBSZ) // 139264
#define AS_OFF (WS_OFF + 34816)    // 174080
#define DSM_WH (AS_OFF + 512 + 1024)

__global__ void __launch_bounds__(256) wh_kernel(const float* __restrict__ h,
                                                 const float* __restrict__ W,
                                                 const float* __restrict__ a) {
    extern __shared__ uint8_t dsm_raw[];
    const uint32_t sb0 = smem_u32(dsm_raw);
    const uint32_t sb = (sb0 + 1023u) & ~1023u;
    uint8_t* dsm = dsm_raw + (sb - sb0);

    const int tid = threadIdx.x, wid = tid >> 5, lid = tid & 31;
    const int row0 = blockIdx.x * 128;

    float* as_p = (float*)(dsm + AS_OFF);
    if (tid < 128) as_p[tid] = a[tid];

    const char* hsrc = (const char*)(h + (size_t)row0 * IND);

#define STAGEH(c)                                                              \
    do {                                                                       \
        const uint32_t hd = sb + HB_OFF + (uint32_t)(((c) & 1) * HBSZ);        \
        _Pragma("unroll")                                                      \
        for (int q = 0; q < 8; q++) {                                          \
            const int idx = tid + 256 * q;                                     \
            const int r = idx >> 4, ch = idx & 15;                             \
            cpa16(hd + (uint32_t)(r * 288 + ch * 16),                          \
                  hsrc + (size_t)r * 1024 + (c) * 256 + ch * 16);              \
        }                                                                      \
    } while (0)

    STAGEH(0);
    cpa_commit();

    // ---- W split staging: [n][k] bf16 hi/lo, chunk-xor swizzle ----
#pragma unroll 4
    for (int q = 0; q < 64; q++) {
        const int idx = tid + 256 * q;
        const int k = idx >> 6, n = idx & 63;
        const float val = __ldg(&W[idx]);
        const uint32_t hh = bf2(val, val) & 0xffffu;
        const float f = __uint_as_float(hh << 16);
        const uint32_t ll = bf2(val - f, val - f) & 0xffffu;
        const uint32_t off =
            (uint32_t)(n * 512 + (((k >> 3) ^ (n & 7)) << 4) + (k & 7) * 2);
        sts16(sb + WHI_OFF + off, (uint16_t)hh);
        sts16(sb + WLO_OFF + off, (uint16_t)ll);
    }

    // ---- per-lane addressing ----
    const int wrow = wid;
    const int r0 = lid >> 2, c0l = (lid & 3) * 2;
    const int g = lid >> 3, rowin = lid & 7, khB = g & 1, nhf = g >> 1;
    const uint32_t abase = (uint32_t)(((wrow * 16 + r0) * 72 + c0l) * 4);
    uint32_t nbase[4], nxr[4];
#pragma unroll
    for (int nb = 0; nb < 4; nb++) {
        const int n = nb * 16 + nhf * 8 + rowin;
        nbase[nb] = (uint32_t)(n * 512);
        nxr[nb] = (uint32_t)(n & 7);
    }

    float4 acc[8];
#pragma unroll
    for (int nt = 0; nt < 8; nt++) acc[nt] = make_float4(0.f, 0.f, 0.f, 0.f);

    for (int c = 0; c < 4; c++) {
        cpa_wait0();
        __syncthreads();   // chunk c ready; also makes W stores visible (c==0)
        if (c < 3) {
            STAGEH(c + 1);
            cpa_commit();
        }
        const uint32_t hb = sb + HB_OFF + (uint32_t)((c & 1) * HBSZ);
#pragma unroll
        for (int ks = 0; ks < 4; ks++) {
            const uint32_t ab = hb + abase + (uint32_t)(ks * 64);
            const float2 q00 = lds_f2(ab);            // (r0,   k0-1)
            const float2 q01 = lds_f2(ab + 2304);     // (r0+8, k0-1)
            const float2 q10 = lds_f2(ab + 32);       // (r0,   k8-9)
            const float2 q11 = lds_f2(ab + 2304 + 32);// (r0+8, k8-9)

            uint32_t ah[4], al[4];
            {
                const uint32_t h0 = bf2(q00.x, q00.y);
                const uint32_t h1 = bf2(q01.x, q01.y);
                const uint32_t h2 = bf2(q10.x, q10.y);
                const uint32_t h3 = bf2(q11.x, q11.y);
                ah[0] = h0; ah[1] = h1; ah[2] = h2; ah[3] = h3;
                al[0] = bf2(q00.x - __uint_as_float(h0 << 16),
                            q00.y - __uint_as_float(h0 & 0xffff0000u));
                al[1] = bf2(q01.x - __uint_as_float(h1 << 16),
                            q01.y - __uint_as_float(h1 & 0xffff0000u));
                al[2] = bf2(q10.x - __uint_as_float(h2 << 16),
                            q10.y - __uint_as_float(h2 & 0xffff0000u));
                al[3] = bf2(q11.x - __uint_as_float(h3 << 16),
                            q11.y - __uint_as_float(h3 & 0xffff0000u));
            }

            const uint32_t chx = (uint32_t)((c * 4 + ks) * 2 + khB);
#pragma unroll
            for (int nb = 0; nb < 4; nb++) {
                const uint32_t addr =
                    sb + WHI_OFF + nbase[nb] + ((chx ^ nxr[nb]) << 4);
                uint32_t bh0, bh1, bh2, bh3, bl0, bl1, bl2, bl3;
                ldmx4(bh0, bh1, bh2, bh3, addr);
                ldmx4(bl0, bl1, bl2, bl3, addr + 32768);
                float* d0 = (float*)&acc[2 * nb];
                float* d1 = (float*)&acc[2 * nb + 1];
                mma16816(d0, ah[0], ah[1], ah[2], ah[3], bh0, bh1);
                mma16816(d0, al[0], al[1], al[2], al[3], bh0, bh1);
                mma16816(d0, ah[0], ah[1], ah[2], ah[3], bl0, bl1);
                mma16816(d1, ah[0], ah[1], ah[2], ah[3], bh2, bh3);
                mma16816(d1, al[0], al[1], al[2], al[3], bh2, bh3);
                mma16816(d1, ah[0], ah[1], ah[2], ah[3], bl2, bl3);
            }
        }
    }
#undef STAGEH

    // ---- write fp32 result to ws ----
    float* wsp = (float*)(dsm + WS_OFF);
#pragma unroll
    for (int nb = 0; nb < 4; nb++)
#pragma unroll
        for (int hf = 0; hf < 2; hf++) {
            const float4 v = acc[2 * nb + hf];
            const int col = nb * 16 + hf * 8 + c0l;
            const int rl = wrow * 16 + r0;
            *(float2*)&wsp[rl * 68 + col] = make_float2(v.x, v.y);
            *(float2*)&wsp[(rl + 8) * 68 + col] = make_float2(v.z, v.w);
        }
    __syncthreads();

    // ---- s1/s2: warp w rows w*16 + lid/2; 2 lanes per row ----
    {
        const int row = wrow * 16 + (lid >> 1);
        const int cb = (lid & 1) * 32;
        float s1 = 0.f, s2 = 0.f;
#pragma unroll 8
        for (int cc = 0; cc < 32; cc++) {
            const float v = wsp[row * 68 + cb + cc];
            s1 = fmaf(v, as_p[cb + cc], s1);
            s2 = fmaf(v, as_p[64 + cb + cc], s2);
        }
        s1 += __shfl_xor_sync(0xffffffffu, s1, 1);
        s2 += __shfl_xor_sync(0xffffffffu, s2, 1);
        if ((lid & 1) == 0) {
            g_s1[row0 + row] = s1;
            g_s2[row0 + row] = s2;
        }
    }

    // ---- bf16-split transpose: thread d = tid&63, rows rg*32..+31 ----
    {
        const int d = tid & 63, rg = tid >> 6;
        uint32_t hi16[16], lo16[16];
#pragma unroll
        for (int p = 0; p < 16; p++) {
            const float p0 = wsp[(rg * 32 + 2 * p) * 68 + d];
            const float p1 = wsp[(rg * 32 + 2 * p + 1) * 68 + d];
            const uint32_t h2 = bf2(p0, p1);
            const float f0 = __uint_as_float(h2 << 16);
            const float f1 = __uint_as_float(h2 & 0xffff0000u);
            hi16[p] = h2;
            lo16[p] = bf2(p0 - f0, p1 - f1);
        }
        const size_t bb = (size_t)(row0 >> 11);
        const int j0l = (row0 & (NN - 1)) + rg * 32;
        char* dst = (char*)g_B + ((bb * DD + d) * NN + j0l) * 2;
#pragma unroll
        for (int qq = 0; qq < 4; qq++) {
            *(uint4*)(dst + qq * 16) = make_uint4(hi16[4 * qq], hi16[4 * qq + 1],
                                                  hi16[4 * qq + 2], hi16[4 * qq + 3]);
            *(uint4*)(dst + LOOFF + qq * 16) =
                make_uint4(lo16[4 * qq], lo16[4 * qq + 1], lo16[4 * qq + 2],
                           lo16[4 * qq + 3]);
        }
    }
}

// ================= Kernel 2: masked-softmax x Wh, adj staged via cp.async =================
// 512 threads, 128 rows/CTA, grid 128. 16 warps = 8 row-blocks x 2 K-split.
#define BSTG 16384
#define ASTG 34816                 // 128 rows * 272 B
#define AOFF (4 * BSTG)            // 65536
#define S2OFF (AOFF + 4 * ASTG)    // 204800
#define DSM_BYTES (S2OFF + 8192 + 1024)

__global__ void __launch_bounds__(512, 1) attn_kernel(const int* __restrict__ adj,
                                                      float* __restrict__ out) {
    extern __shared__ uint8_t dsm_raw[];
    uint32_t sb = smem_u32(dsm_raw);
    sb = (sb + 1023u) & ~1023u;

    const int tid = threadIdx.x, wid = tid >> 5, lid = tid & 31;
    const int wg = wid >> 3;
    const int wrow = wid & 7;
    const int b = blockIdx.x >> 4;
    const int i0 = (blockIdx.x & 15) * 128;
    const int ibase = i0 + wrow * 16;
    const int r0 = lid >> 2, c0 = (lid & 3) * 2;

    const float s1_0 = g_s1[b * NN + ibase + r0];
    const float s1_1 = g_s1[b * NN + ibase + r0 + 8];
    float den0 = 0.f, den1 = 0.f;
    float4 acc[8];
#pragma unroll
    for (int nt = 0; nt < 8; nt++) acc[nt] = make_float4(0.f, 0.f, 0.f, 0.f);

    uint32_t nrel[4], nxor[4], kh;
    {
        const int g = lid >> 3, rowin = lid & 7;
        kh = (uint32_t)((g & 1) * 16);
#pragma unroll
        for (int np = 0; np < 4; np++) {
            const int n = np * 16 + (g >> 1) * 8 + rowin;
            nrel[np] = (uint32_t)(n * 128);
            nxor[np] = (uint32_t)((n & 7) << 4);
        }
    }

    const char* gbh = (const char*)g_B + (size_t)b * DD * NN * 2;
    const uint32_t ssw0 = sw128((uint32_t)((tid >> 3) * 128 + (tid & 7) * 16));
    const uint32_t sgo0 = (uint32_t)((tid >> 3) * NN * 2 + (tid & 7) * 16);

    const char* gadj = (const char*)(adj + ((size_t)b * NN + i0) * NN);

#define STAGE(t)                                                               \
    do {                                                                       \
        const uint32_t bd = sb + (((t) & 3) * BSTG);                           \
        const size_t go = (size_t)(t) * (KTILE * 2);                           \
        cpa16(bd + ssw0, gbh + sgo0 + go);                                     \
        cpa16(bd + ssw0 + 8192, gbh + sgo0 + go + LOOFF);                      \
        const uint32_t ad = sb + AOFF + (((t) & 3) * ASTG);                    \
        const size_t jb = (size_t)(t) * (KTILE * 4);                           \
        _Pragma("unroll")                                                      \
        for (int q = 0; q < 4; q++) {                                          \
            const int idx = tid + 512 * q;                                     \
            const int rr_ = idx >> 4, ch_ = idx & 15;                          \
            cpa16(ad + rr_ * 272 + ch_ * 16,                                   \
                  gadj + (size_t)rr_ * (NN * 4) + jb + ch_ * 16);              \
        }                                                                      \
    } while (0)

    cpa16(sb + S2OFF + tid * 16, (const char*)(g_s2 + b * NN) + tid * 16);
    STAGE(0);
    STAGE(1);
    cpa_commit();

    const uint32_t arow_base = (uint32_t)((wrow * 16 + r0) * 272);

    for (int i = 0; i < NKT / 2; i++) {
        cpa_wait0();
        __syncthreads();
        if (i < NKT / 2 - 1) {
            STAGE(2 * i + 2);
            STAGE(2 * i + 3);
            cpa_commit();
        }

        const int t = 2 * i + wg;
        const uint32_t bufb = sb + ((t & 3) * BSTG);
        const uint32_t abuf = sb + AOFF + ((t & 3) * ASTG) + arow_base;

#pragma unroll
        for (int ks = 0; ks < 4; ks++) {
            const uint32_t jcb = (uint32_t)((ks * 16 + c0) * 4);
            const int2 aj0 = lds_i2(abuf + jcb);
            const int2 aj1 = lds_i2(abuf + jcb + 32);
            const int2 aj2 = lds_i2(abuf + 8 * 272 + jcb);
            const int2 aj3 = lds_i2(abuf + 8 * 272 + jcb + 32);
            const uint32_t s2ad = sb + S2OFF + (uint32_t)((t * 64 + ks * 16 + c0) * 4);
            const float2 s2a = lds_f2(s2ad);
            const float2 s2b = lds_f2(s2ad + 32);

            const float p0 = pe(s1_0 + s2a.x, aj0.x);
            const float p1 = pe(s1_0 + s2a.y, aj0.y);
            const float p2 = pe(s1_0 + s2b.x, aj1.x);
            const float p3 = pe(s1_0 + s2b.y, aj1.y);
            const float p4 = pe(s1_1 + s2a.x, aj2.x);
            const float p5 = pe(s1_1 + s2a.y, aj2.y);
            const float p6 = pe(s1_1 + s2b.x, aj3.x);
            const float p7 = pe(s1_1 + s2b.y, aj3.y);
            den0 += (p0 + p1) + (p2 + p3);
            den1 += (p4 + p5) + (p6 + p7);

            uint32_t ah[4], al[4];
            {
                const uint32_t h0 = bf2(p0, p1), h1 = bf2(p4, p5);
                const uint32_t h2 = bf2(p2, p3), h3 = bf2(p6, p7);
                ah[0] = h0; ah[1] = h1; ah[2] = h2; ah[3] = h3;
                al[0] = bf2(p0 - __uint_as_float(h0 << 16),
                            p1 - __uint_as_float(h0 & 0xffff0000u));
                al[1] = bf2(p4 - __uint_as_float(h1 << 16),
                            p5 - __uint_as_float(h1 & 0xffff0000u));
                al[2] = bf2(p2 - __uint_as_float(h2 << 16),
                            p3 - __uint_as_float(h2 & 0xffff0000u));
                al[3] = bf2(p6 - __uint_as_float(h3 << 16),
                            p7 - __uint_as_float(h3 & 0xffff0000u));
            }

#pragma unroll
            for (int np = 0; np < 4; np++) {
                const uint32_t off = ((uint32_t)(ks * 32) + kh) ^ nxor[np];
                const uint32_t addr = bufb + nrel[np] + off;
                uint32_t h0, h1, h2, h3, l0, l1, l2, l3;
                ldmx4(h0, h1, h2, h3, addr);
                ldmx4(l0, l1, l2, l3, addr + 8192);
                float* d0 = (float*)&acc[2 * np];
                float* d1 = (float*)&acc[2 * np + 1];
                mma16816(d0, ah[0], ah[1], ah[2], ah[3], h0, h1);
                mma16816(d0, al[0], al[1], al[2], al[3], h0, h1);
                mma16816(d0, ah[0], ah[1], ah[2], ah[3], l0, l1);
                mma16816(d1, ah[0], ah[1], ah[2], ah[3], h2, h3);
                mma16816(d1, al[0], al[1], al[2], al[3], h2, h3);
                mma16816(d1, ah[0], ah[1], ah[2], ah[3], l2, l3);
            }
        }
    }
#undef STAGE

    __syncthreads();

    {
        float* redp = (float*)(dsm_raw + (sb - smem_u32(dsm_raw)));
        float* slot = redp + (size_t)(wrow * 32 + lid) * 36;
        if (wg == 1) {
#pragma unroll
            for (int nt = 0; nt < 8; nt++) *(float4*)(slot + nt * 4) = acc[nt];
            slot[32] = den0;
            slot[33] = den1;
        }
        __syncthreads();
        if (wg == 0) {
#pragma unroll
            for (int nt = 0; nt < 8; nt++) {
                const float4 v = *(const float4*)(slot + nt * 4);
                acc[nt].x += v.x; acc[nt].y += v.y;
                acc[nt].z += v.z; acc[nt].w += v.w;
            }
            den0 += slot[32];
            den1 += slot[33];

            den0 += __shfl_xor_sync(0xffffffffu, den0, 1);
            den0 += __shfl_xor_sync(0xffffffffu, den0, 2);
            den1 += __shfl_xor_sync(0xffffffffu, den1, 1);
            den1 += __shfl_xor_sync(0xffffffffu, den1, 2);
            const float inv0 = 1.0f / den0;
            const float inv1 = 1.0f / den1;

            float* o0 = out + (size_t)(b * NN + ibase + r0) * DD;
            float* o1 = o0 + (size_t)8 * DD;
#pragma unroll
            for (int nt = 0; nt < 8; nt++) {
                *(float2*)(o0 + nt * 8 + c0) =
                    make_float2(acc[nt].x * inv0, acc[nt].y * inv0);
                *(float2*)(o1 + nt * 8 + c0) =
                    make_float2(acc[nt].z * inv1, acc[nt].w * inv1);
            }
        }
    }
}

extern "C" void kernel_launch(void* const* d_in, const int* in_sizes, int n_in,
                              void* d_out, int out_size) {
    const float* h = nullptr;
    const int* adj = nullptr;
    const float* W = nullptr;
    const float* a = nullptr;
    for (int i = 0; i < n_in; i++) {
        const long long s = in_sizes[i];
        if (s == (long long)BB * NN * IND)      h   = (const float*)d_in[i];
        else if (s == (long long)BB * NN * NN)  adj = (const int*)d_in[i];
        else if (s == (long long)IND * DD)      W   = (const float*)d_in[i];
        else if (s == 2 * DD)                   a   = (const float*)d_in[i];
    }
    float* out = (float*)d_out;

    static bool attr_set = false;
    if (!attr_set) {
        cudaFuncSetAttribute(attn_kernel, cudaFuncAttributeMaxDynamicSharedMemorySize,
                             DSM_BYTES);
        cudaFuncSetAttribute(wh_kernel, cudaFuncAttributeMaxDynamicSharedMemorySize,
                             DSM_WH);
        attr_set = true;
    }

    wh_kernel<<<(BB * NN) / 128, 256, DSM_WH>>>(h, W, a);
    attn_kernel<<<BB * (NN / 128), 512, DSM_BYTES>>>(adj, out);
}